// round 2
// baseline (speedup 1.0000x reference)
#include <cuda_runtime.h>

// Row-wise cumulative product, rows of 32768 fp32, one CTA per row.
// Tiled block-scan: 1024 threads x float4 = 4096 elems/tile, 8 tiles/row,
// multiplicative carry chained across tiles. Prefetch next tile before the
// scan of the current tile to overlap HBM latency with shuffle work.
// warp_prod is double-buffered so no trailing barrier is needed per tile.

#define COLS        32768
#define THREADS     1024
#define VEC         4
#define TILE_ELEMS  (THREADS * VEC)          // 4096
#define NTILES      (COLS / TILE_ELEMS)      // 8

__global__ __launch_bounds__(THREADS, 2)
void cumprod_rows_kernel(const float4* __restrict__ in, float4* __restrict__ out)
{
    const int row  = blockIdx.x;
    const int t    = threadIdx.x;
    const int lane = t & 31;
    const int warp = t >> 5;

    const float4* rin  = in  + (size_t)row * (COLS / VEC);
    float4*       rout = out + (size_t)row * (COLS / VEC);

    __shared__ float warp_prod[2][32];

    float carry = 1.0f;

    // prefetch tile 0
    float4 v = rin[t];

    #pragma unroll
    for (int tile = 0; tile < NTILES; ++tile) {
        const int buf = tile & 1;
        float4 cur = v;
        // prefetch next tile while we scan this one
        if (tile + 1 < NTILES)
            v = rin[(tile + 1) * THREADS + t];

        // thread-local inclusive products
        float p0 = cur.x;
        float p1 = p0 * cur.y;
        float p2 = p1 * cur.z;
        float p3 = p2 * cur.w;

        // warp inclusive multiplicative scan of p3
        float incl = p3;
        #pragma unroll
        for (int o = 1; o < 32; o <<= 1) {
            float n = __shfl_up_sync(0xffffffffu, incl, o);
            if (lane >= o) incl *= n;
        }

        // lane-exclusive prefix within warp
        float excl = __shfl_up_sync(0xffffffffu, incl, 1);
        if (lane == 0) excl = 1.0f;

        if (lane == 31) warp_prod[buf][warp] = incl;
        __syncthreads();

        // warp 0 scans the 32 warp totals
        if (warp == 0) {
            float w = warp_prod[buf][lane];
            #pragma unroll
            for (int o = 1; o < 32; o <<= 1) {
                float n = __shfl_up_sync(0xffffffffu, w, o);
                if (lane >= o) w *= n;
            }
            warp_prod[buf][lane] = w;
        }
        __syncthreads();

        float prefix = carry * excl;
        if (warp > 0) prefix *= warp_prod[buf][warp - 1];

        float4 o4;
        o4.x = prefix * p0;
        o4.y = prefix * p1;
        o4.z = prefix * p2;
        o4.w = prefix * p3;
        rout[tile * THREADS + t] = o4;

        // advance carry by this tile's total product
        carry *= warp_prod[buf][31];
        // no trailing barrier: next tile writes the OTHER buffer
    }
}

extern "C" void kernel_launch(void* const* d_in, const int* in_sizes, int n_in,
                              void* d_out, int out_size)
{
    const float* x = (const float*)d_in[0];
    float*       y = (float*)d_out;
    const int total = in_sizes[0];
    const int rows  = total / COLS;

    cumprod_rows_kernel<<<rows, THREADS>>>((const float4*)x, (float4*)y);
}

// round 3
// speedup vs baseline: 1.2448x; 1.2448x over previous
#include <cuda_runtime.h>

// Row-wise cumulative product, rows of 32768 fp32, one CTA per row.
// 1024 threads x float4 = 4096 elems/tile, 8 tiles/row, multiplicative carry.
// Single barrier per tile: every warp redundantly scans the 32 warp totals
// (shuffle scan) instead of funneling through warp 0 + a second barrier.
// Streaming cache hints (__ldcs/__stcs): zero reuse, keep L2 clean.

#define COLS        32768
#define THREADS     1024
#define VEC         4
#define TILE_ELEMS  (THREADS * VEC)          // 4096
#define NTILES      (COLS / TILE_ELEMS)      // 8

__global__ __launch_bounds__(THREADS, 2)
void cumprod_rows_kernel(const float4* __restrict__ in, float4* __restrict__ out)
{
    const int row  = blockIdx.x;
    const int t    = threadIdx.x;
    const int lane = t & 31;
    const int warp = t >> 5;

    const float4* rin  = in  + (size_t)row * (COLS / VEC);
    float4*       rout = out + (size_t)row * (COLS / VEC);

    __shared__ float warp_prod[2][32];

    float carry = 1.0f;

    // prefetch tile 0 (evict-first: no reuse)
    float4 v = __ldcs(&rin[t]);

    #pragma unroll
    for (int tile = 0; tile < NTILES; ++tile) {
        const int buf = tile & 1;
        float4 cur = v;
        // prefetch next tile while we scan this one
        if (tile + 1 < NTILES)
            v = __ldcs(&rin[(tile + 1) * THREADS + t]);

        // thread-local inclusive products
        float p0 = cur.x;
        float p1 = p0 * cur.y;
        float p2 = p1 * cur.z;
        float p3 = p2 * cur.w;

        // warp inclusive multiplicative scan of p3
        float incl = p3;
        #pragma unroll
        for (int o = 1; o < 32; o <<= 1) {
            float n = __shfl_up_sync(0xffffffffu, incl, o);
            if (lane >= o) incl *= n;
        }

        // lane-exclusive prefix within warp
        float excl = __shfl_up_sync(0xffffffffu, incl, 1);
        if (lane == 0) excl = 1.0f;

        if (lane == 31) warp_prod[buf][warp] = incl;
        __syncthreads();   // the ONLY barrier this tile

        // every warp scans the 32 warp totals itself (redundant, but removes
        // the second barrier and the warp-0 serialization)
        float w = warp_prod[buf][lane];
        #pragma unroll
        for (int o = 1; o < 32; o <<= 1) {
            float n = __shfl_up_sync(0xffffffffu, w, o);
            if (lane >= o) w *= n;
        }
        // exclusive prefix over warps for THIS warp, and tile total
        const int src   = (warp == 0) ? 0 : (warp - 1);
        float wexcl     = __shfl_sync(0xffffffffu, w, src);
        if (warp == 0) wexcl = 1.0f;
        const float tot = __shfl_sync(0xffffffffu, w, 31);

        const float prefix = carry * wexcl * excl;

        float4 o4;
        o4.x = prefix * p0;
        o4.y = prefix * p1;
        o4.z = prefix * p2;
        o4.w = prefix * p3;
        __stcs(&rout[tile * THREADS + t], o4);

        carry *= tot;
        // no trailing barrier: next tile writes the OTHER warp_prod buffer,
        // and all reads of this buffer precede the next barrier arrival.
    }
}

extern "C" void kernel_launch(void* const* d_in, const int* in_sizes, int n_in,
                              void* d_out, int out_size)
{
    const float* x = (const float*)d_in[0];
    float*       y = (float*)d_out;
    const int total = in_sizes[0];
    const int rows  = total / COLS;

    cumprod_rows_kernel<<<rows, THREADS>>>((const float4*)x, (float4*)y);
}